// round 6
// baseline (speedup 1.0000x reference)
#include <cuda_runtime.h>
#include <cstdint>

#define N_BOX     8192
#define MAX_KEEP  256
#define MIN_SCORE 0.3f
#define NMS_THR   0.3f
#define NT        1024
#define NBKT      4096
#define WIN       1024
#define RES       64
#define FULL      0xFFFFFFFFu

extern __shared__ unsigned char dynsmem[];

__global__ void __launch_bounds__(NT, 1)
detect_kernel(const float* __restrict__ score,
              const float* __restrict__ box,
              float* __restrict__ out)
{
    // ---- dynamic smem (192 KB) ----
    // [0,128K)    s_cbox : sorted candidate bbox xyxy (float4)  [phase 1 overlay: cnt/off]
    // [128K,192K) s_key  : sorted u64 keys (~score_bits, idx)
    float4*             s_cbox = (float4*)dynsmem;
    unsigned long long* s_key  = (unsigned long long*)(dynsmem + 131072);
    unsigned int*       s_cnt  = (unsigned int*)dynsmem;
    unsigned int*       s_off  = (unsigned int*)(dynsmem + 16384);

    __shared__ float4 s_kbox[MAX_KEEP];
    __shared__ float  s_kar[MAX_KEEP];
    __shared__ float  s_ksc[MAX_KEEP];
    __shared__ int    s_kid[MAX_KEEP];
    __shared__ float4 s_cb[RES];
    __shared__ int    s_gidx[RES];
    __shared__ unsigned long long s_row[RES];
    __shared__ int    s_list[WIN];
    __shared__ int    s_wcnt[32], s_woff[32];
    __shared__ unsigned int s_wsum[32];
    __shared__ int s_nvalid, s_kc, s_pos, s_nalive;

    const int tid  = threadIdx.x;
    const int lane = tid & 31;
    const int wid  = tid >> 5;

    // ================= phase 1: bucket sort (exact stable descending) =================
    for (int i = tid; i < NBKT; i += NT) s_cnt[i] = 0;
    if (tid == 0) s_kc = 0;
    __syncthreads();

    float sc[8]; int bk[8];
    #pragma unroll
    for (int k = 0; k < 8; k++) {
        int i = tid + k * NT;
        float s = score[i];
        sc[k] = s;
        int b = -1;
        if (s >= MIN_SCORE) {
            b = 4095 - min(4095, (int)(s * 4096.0f));   // score desc -> bucket asc (monotone)
            atomicAdd(&s_cnt[b], 1u);
        }
        bk[k] = b;
    }
    __syncthreads();

    unsigned int c0 = s_cnt[tid*4+0], c1 = s_cnt[tid*4+1], c2 = s_cnt[tid*4+2], c3 = s_cnt[tid*4+3];
    unsigned int tsum = c0 + c1 + c2 + c3;
    unsigned int p = tsum;
    #pragma unroll
    for (int d = 1; d < 32; d <<= 1) {
        unsigned int v = __shfl_up_sync(FULL, p, d);
        if (lane >= d) p += v;
    }
    if (lane == 31) s_wsum[wid] = p;
    __syncthreads();
    if (wid == 0) {
        unsigned int w = s_wsum[lane];
        unsigned int q = w;
        #pragma unroll
        for (int d = 1; d < 32; d <<= 1) {
            unsigned int v = __shfl_up_sync(FULL, q, d);
            if (lane >= d) q += v;
        }
        s_wsum[lane] = q - w;
        if (lane == 31) s_nvalid = (int)q;
    }
    __syncthreads();
    unsigned int basep = s_wsum[wid] + (p - tsum);
    s_off[tid*4+0] = basep;
    s_off[tid*4+1] = basep + c0;
    s_off[tid*4+2] = basep + c0 + c1;
    s_off[tid*4+3] = basep + c0 + c1 + c2;
    __syncthreads();

    #pragma unroll
    for (int k = 0; k < 8; k++) {
        if (bk[k] >= 0) {
            int i = tid + k * NT;
            unsigned int pos = atomicAdd(&s_off[bk[k]], 1u);
            s_key[pos] = ((unsigned long long)(~__float_as_uint(sc[k])) << 32) | (unsigned int)i;
        }
    }
    __syncthreads();

    for (int b = tid; b < NBKT; b += NT) {
        int lo = b ? (int)s_off[b-1] : 0;
        int hi = (int)s_off[b];
        for (int i = lo + 1; i < hi; i++) {
            unsigned long long v = s_key[i];
            int j = i - 1;
            while (j >= lo && s_key[j] > v) { s_key[j+1] = s_key[j]; j--; }
            s_key[j+1] = v;
        }
    }
    __syncthreads();               // sort done; cnt/off regions dead from here

    const int nval = s_nvalid;

    // ========== phase 1.5: pre-gather candidate boxes (xyxy) into smem ==========
    for (int c = tid; c < nval; c += NT) {
        int idx = (int)(s_key[c] & 0xFFFFFFFFull);
        float4 b4 = *(const float4*)(box + idx * 16);
        float hw = b4.z * 0.5f, hh = b4.w * 0.5f;
        s_cbox[c] = make_float4(b4.x - hw, b4.y - hh, b4.x + hw, b4.y + hh);
    }
    __syncthreads();

    // ================= phase 2: windowed greedy NMS =================
    int kc = 0, pos = 0;
    while (pos < nval && kc < MAX_KEEP) {
        const int W = min(WIN, nval - pos);

        // ---- 1) kept-filter: thread tid owns candidate pos+tid ----
        bool aliveF = false;
        if (tid < W) {
            int c = pos + tid;
            float4 b = s_cbox[c];
            float arb = (b.z - b.x) * (b.w - b.y);
            aliveF = true;
            for (int k = 0; k < kc; k++) {
                float4 K = s_kbox[k];
                float lx = fmaxf(K.x, b.x), ly = fmaxf(K.y, b.y);
                float rx = fminf(K.z, b.z), ry = fminf(K.w, b.w);
                float inter = fmaxf(rx - lx, 0.0f) * fmaxf(ry - ly, 0.0f);
                if (inter / (s_kar[k] + arb - inter + 1e-9f) > NMS_THR) { aliveF = false; break; }
            }
        }
        unsigned int bal = __ballot_sync(FULL, aliveF);
        if (lane == 0) s_wcnt[wid] = __popc(bal);
        __syncthreads();

        // ---- 2) warp0: exclusive scan of warp counts ----
        if (wid == 0) {
            int v = s_wcnt[lane];
            int q = v;
            #pragma unroll
            for (int d = 1; d < 32; d <<= 1) {
                int u = __shfl_up_sync(FULL, q, d);
                if (lane >= d) q += u;
            }
            s_woff[lane] = q - v;
            if (lane == 31) s_nalive = q;
        }
        __syncthreads();

        // ---- 3) ordered compaction + stage first RES survivors ----
        if (aliveF) {
            int rank = s_woff[wid] + __popc(bal & ((1u << lane) - 1u));
            int c = pos + tid;
            s_list[rank] = c;
            if (rank < RES) { s_cb[rank] = s_cbox[c]; s_gidx[rank] = c; }
        }
        __syncthreads();

        const int nalive = s_nalive;
        if (nalive == 0) { pos += W; continue; }
        const int m = min(nalive, RES);

        // ---- 4) mutual IoU rows among the m staged (warp wid: rows 2wid, 2wid+1) ----
        float4 cbx0 = s_cb[lane];                                    // guarded by lane<m below
        float4 cbx1 = (32 + lane < m) ? s_cb[32 + lane] : make_float4(0,0,0,0);
        float ar0 = (cbx0.z - cbx0.x) * (cbx0.w - cbx0.y);
        float ar1 = (cbx1.z - cbx1.x) * (cbx1.w - cbx1.y);
        #pragma unroll
        for (int rr = 0; rr < 2; rr++) {
            int r = (wid << 1) | rr;
            if (r < m) {
                float4 B  = s_cb[r];
                float  AR = (B.z - B.x) * (B.w - B.y);

                float lx = fmaxf(B.x, cbx0.x), ly = fmaxf(B.y, cbx0.y);
                float rx = fminf(B.z, cbx0.z), ry = fminf(B.w, cbx0.w);
                float inter = fmaxf(rx - lx, 0.0f) * fmaxf(ry - ly, 0.0f);
                bool hit0 = (lane < m) && (inter / (AR + ar0 - inter + 1e-9f) > NMS_THR);

                lx = fmaxf(B.x, cbx1.x); ly = fmaxf(B.y, cbx1.y);
                rx = fminf(B.z, cbx1.z); ry = fminf(B.w, cbx1.w);
                inter = fmaxf(rx - lx, 0.0f) * fmaxf(ry - ly, 0.0f);
                bool hit1 = (32 + lane < m) && (inter / (AR + ar1 - inter + 1e-9f) > NMS_THR);

                unsigned int m0 = __ballot_sync(FULL, hit0);
                unsigned int m1 = __ballot_sync(FULL, hit1);
                if (lane == 0)
                    s_row[r] = (unsigned long long)m0 | ((unsigned long long)m1 << 32);
            }
        }
        __syncthreads();

        // ---- 5) lane-0 serial greedy resolve over the m staged (all pre-cleared vs kept) ----
        if (tid == 0) {
            unsigned long long alive = (m == RES) ? ~0ull : ((1ull << m) - 1ull);
            int kcl = kc;
            while (alive && kcl < MAX_KEEP) {
                int t = __ffsll((long long)alive) - 1;
                float4 bb = s_cb[t];
                s_kbox[kcl] = bb;
                s_kar[kcl]  = (bb.z - bb.x) * (bb.w - bb.y);
                unsigned long long key = s_key[s_gidx[t]];
                s_kid[kcl] = (int)(key & 0xFFFFFFFFull);
                s_ksc[kcl] = __uint_as_float(~(unsigned int)(key >> 32));
                kcl++;
                alive &= ~s_row[t];
                alive &= ~(1ull << t);      // retire even if degenerate self-IoU
            }
            s_kc  = kcl;
            s_pos = s_gidx[m - 1] + 1;      // all alive before this are resolved; dead stay dead
        }
        __syncthreads();
        kc  = s_kc;
        pos = s_pos;
    }

    // ================= outputs =================
    // layout: [0,256) score | [256,4352) box (256x16) | [4352,4608) valid
    for (int k = tid; k < MAX_KEEP; k += NT) {
        bool v = k < kc;
        out[k]        = v ? s_ksc[k] : 0.0f;
        out[4352 + k] = v ? 1.0f : 0.0f;
    }
    for (int e = tid; e < MAX_KEEP * 16; e += NT) {
        int k = e >> 4, c = e & 15;
        out[256 + e] = (k < kc) ? box[s_kid[k] * 16 + c] : 0.0f;
    }
}

// ---------------- launch ----------------
extern "C" void kernel_launch(void* const* d_in, const int* in_sizes, int n_in,
                              void* d_out, int out_size) {
    const float* score = (const float*)d_in[0];
    const float* box   = (const float*)d_in[1];
    float* out = (float*)d_out;

    const int dyn = 196608;   // 192 KB
    cudaFuncSetAttribute(detect_kernel,
                         cudaFuncAttributeMaxDynamicSharedMemorySize, dyn);
    detect_kernel<<<1, NT, dyn>>>(score, box, out);
}

// round 7
// speedup vs baseline: 2.4844x; 2.4844x over previous
#include <cuda_runtime.h>
#include <cstdint>

#define N_BOX     8192
#define MAX_KEEP  256
#define MIN_SCORE 0.3f
#define NMS_THR   0.3f
#define NT        1024
#define NBKT      4096
#define NCHUNK    128          // 8192 / 64
#define FULL      0xFFFFFFFFu

// ---------------- global scratch (static __device__, no allocation) ----------------
__device__ unsigned long long g_key[N_BOX];        // sorted keys (~score_bits, idx)
__device__ float4             g_cbox[N_BOX];       // sorted xyxy boxes
__device__ unsigned long long g_mask[N_BOX * NCHUNK];  // 8 MB suppression bitmask
__device__ int                g_nval;

// ================= kernel A: bucket sort (exact stable descending) =================
extern __shared__ unsigned char dynsmem[];

__global__ void __launch_bounds__(NT, 1)
sort_kernel(const float* __restrict__ score, const float* __restrict__ box)
{
    unsigned long long* s_key = (unsigned long long*)dynsmem;          // 64 KB
    unsigned int*       s_cnt = (unsigned int*)(dynsmem + 65536);      // 16 KB
    unsigned int*       s_off = (unsigned int*)(dynsmem + 81920);      // 16 KB
    __shared__ unsigned int s_wsum[32];
    __shared__ int s_nvalid;

    const int tid  = threadIdx.x;
    const int lane = tid & 31;
    const int wid  = tid >> 5;

    for (int i = tid; i < NBKT; i += NT) s_cnt[i] = 0;
    __syncthreads();

    float sc[8]; int bk[8];
    #pragma unroll
    for (int k = 0; k < 8; k++) {
        int i = tid + k * NT;
        float s = score[i];
        sc[k] = s;
        int b = -1;
        if (s >= MIN_SCORE) {
            b = 4095 - min(4095, (int)(s * 4096.0f));   // score desc -> bucket asc (monotone)
            atomicAdd(&s_cnt[b], 1u);
        }
        bk[k] = b;
    }
    __syncthreads();

    unsigned int c0 = s_cnt[tid*4+0], c1 = s_cnt[tid*4+1], c2 = s_cnt[tid*4+2], c3 = s_cnt[tid*4+3];
    unsigned int tsum = c0 + c1 + c2 + c3;
    unsigned int p = tsum;
    #pragma unroll
    for (int d = 1; d < 32; d <<= 1) {
        unsigned int v = __shfl_up_sync(FULL, p, d);
        if (lane >= d) p += v;
    }
    if (lane == 31) s_wsum[wid] = p;
    __syncthreads();
    if (wid == 0) {
        unsigned int w = s_wsum[lane];
        unsigned int q = w;
        #pragma unroll
        for (int d = 1; d < 32; d <<= 1) {
            unsigned int v = __shfl_up_sync(FULL, q, d);
            if (lane >= d) q += v;
        }
        s_wsum[lane] = q - w;
        if (lane == 31) s_nvalid = (int)q;
    }
    __syncthreads();
    unsigned int basep = s_wsum[wid] + (p - tsum);
    s_off[tid*4+0] = basep;
    s_off[tid*4+1] = basep + c0;
    s_off[tid*4+2] = basep + c0 + c1;
    s_off[tid*4+3] = basep + c0 + c1 + c2;
    __syncthreads();

    #pragma unroll
    for (int k = 0; k < 8; k++) {
        if (bk[k] >= 0) {
            int i = tid + k * NT;
            unsigned int pos = atomicAdd(&s_off[bk[k]], 1u);
            s_key[pos] = ((unsigned long long)(~__float_as_uint(sc[k])) << 32) | (unsigned int)i;
        }
    }
    __syncthreads();

    // intra-bucket insertion sort on full u64 key (exact total order)
    for (int b = tid; b < NBKT; b += NT) {
        int lo = b ? (int)s_off[b-1] : 0;
        int hi = (int)s_off[b];
        for (int i = lo + 1; i < hi; i++) {
            unsigned long long v = s_key[i];
            int j = i - 1;
            while (j >= lo && s_key[j] > v) { s_key[j+1] = s_key[j]; j--; }
            s_key[j+1] = v;
        }
    }
    __syncthreads();

    const int nval = s_nvalid;
    for (int c = tid; c < nval; c += NT) {
        unsigned long long key = s_key[c];
        g_key[c] = key;
        int idx = (int)(key & 0xFFFFFFFFull);
        float4 b4 = *(const float4*)(box + idx * 16);
        float hw = b4.z * 0.5f, hh = b4.w * 0.5f;
        g_cbox[c] = make_float4(b4.x - hw, b4.y - hh, b4.x + hw, b4.y + hh);
    }
    if (tid == 0) g_nval = nval;
}

// ================= kernel B: suppression bitmask matrix (multi-SM) =================
// block: 256 threads = 256 rows; grid (32, 128): (row tile, col chunk)
__global__ void __launch_bounds__(256)
mask_kernel()
{
    const int tj = blockIdx.y;               // col chunk 0..127
    const int i0 = blockIdx.x * 256;         // row tile base
    const int nval = g_nval;
    if (i0 >= nval) return;
    if (tj * 64 + 63 <= i0) return;          // whole tile has j <= all rows -> unread

    __shared__ float4 cb[64];
    __shared__ float  car[64];
    const int t = threadIdx.x;
    if (t < 64) {
        int j = tj * 64 + t;
        float4 b = (j < nval) ? g_cbox[j] : make_float4(0,0,0,0);
        cb[t]  = b;
        car[t] = (b.z - b.x) * (b.w - b.y);
    }
    __syncthreads();

    const int i = i0 + t;
    if (i >= nval) return;
    float4 B  = g_cbox[i];
    float  AR = (B.z - B.x) * (B.w - B.y);

    const int qlo  = max(0, i + 1 - tj * 64);             // strict j > i
    const int qmax = min(64, nval - tj * 64);
    unsigned long long w = 0;
    for (int q = qlo; q < qmax; q++) {
        float4 b = cb[q];
        float lx = fmaxf(B.x, b.x), ly = fmaxf(B.y, b.y);
        float rx = fminf(B.z, b.z), ry = fminf(B.w, b.w);
        float inter = fmaxf(rx - lx, 0.0f) * fmaxf(ry - ly, 0.0f);
        if (inter / (AR + car[q] - inter + 1e-9f) > NMS_THR)
            w |= 1ull << q;
    }
    g_mask[i * NCHUNK + tj] = w;
}

// ================= kernel C: serial sweep + output (single block, 256 thr) =================
__global__ void __launch_bounds__(256, 1)
sweep_kernel(const float* __restrict__ box, float* __restrict__ out)
{
    __shared__ unsigned long long rem[NCHUNK];
    __shared__ unsigned long long colbuf[2][64];
    __shared__ int   klist[64];
    __shared__ int   keptidx[MAX_KEEP];
    __shared__ int   s_kc, s_kcn;
    __shared__ int   s_orig[MAX_KEEP];

    const int tid  = threadIdx.x;
    const int nval = g_nval;
    const int nchunk = (nval + 63) >> 6;

    if (tid < NCHUNK) rem[tid] = 0ull;
    if (tid == 0) { s_kc = 0; s_kcn = 0; }
    // preload column for chunk 0
    if (tid < 64 && tid < nval)
        colbuf[0][tid] = g_mask[tid * NCHUNK + 0];
    __syncthreads();

    for (int c = 0; c < nchunk; c++) {
        // prefetch next chunk's diagonal column (threads 192..255) while thread 0 resolves
        if (tid >= 192 && c + 1 < nchunk) {
            int t = tid - 192;
            int i = (c + 1) * 64 + t;
            if (i < nval)
                colbuf[(c + 1) & 1][t] = g_mask[i * NCHUNK + (c + 1)];
        }
        if (tid == 0) {
            int rembits = nval - c * 64;
            unsigned long long validw = (rembits >= 64) ? ~0ull : ((1ull << rembits) - 1ull);
            unsigned long long alive = validw & ~rem[c];
            const unsigned long long* col = colbuf[c & 1];
            int kc = s_kc, n = 0;
            while (alive && kc < MAX_KEEP) {
                int t = __ffsll((long long)alive) - 1;
                keptidx[kc++] = c * 64 + t;
                klist[n++] = t;
                alive &= ~col[t];
                alive &= ~(1ull << t);
            }
            s_kc = kc; s_kcn = n;
        }
        __syncthreads();

        const int n = s_kcn;
        if (n) {
            int w = c + 1 + tid;
            if (w < nchunk) {
                const int base = c * 64;
                unsigned long long acc = 0;
                for (int q = 0; q < n; q++)
                    acc |= g_mask[(base + klist[q]) * NCHUNK + w];
                rem[w] |= acc;
            }
        }
        __syncthreads();
        if (s_kc >= MAX_KEEP) break;
    }

    // ---------------- outputs ----------------
    // layout: [0,256) score | [256,4352) box (256x16) | [4352,4608) valid
    const int kc = s_kc;
    for (int k = tid; k < MAX_KEEP; k += 256) {
        if (k < kc) {
            unsigned long long key = g_key[keptidx[k]];
            s_orig[k]     = (int)(key & 0xFFFFFFFFull);
            out[k]        = __uint_as_float(~(unsigned int)(key >> 32));
            out[4352 + k] = 1.0f;
        } else {
            out[k]        = 0.0f;
            out[4352 + k] = 0.0f;
        }
    }
    __syncthreads();
    for (int e = tid; e < MAX_KEEP * 16; e += 256) {
        int k = e >> 4, c = e & 15;
        out[256 + e] = (k < kc) ? box[s_orig[k] * 16 + c] : 0.0f;
    }
}

// ---------------- launch ----------------
extern "C" void kernel_launch(void* const* d_in, const int* in_sizes, int n_in,
                              void* d_out, int out_size) {
    const float* score = (const float*)d_in[0];
    const float* box   = (const float*)d_in[1];
    float* out = (float*)d_out;

    const int dynA = 98304;   // 64K keys + 16K hist + 16K offsets
    cudaFuncSetAttribute(sort_kernel,
                         cudaFuncAttributeMaxDynamicSharedMemorySize, dynA);

    sort_kernel<<<1, NT, dynA>>>(score, box);
    mask_kernel<<<dim3(32, 128), 256>>>();
    sweep_kernel<<<1, 256>>>(box, out);
}